// round 15
// baseline (speedup 1.0000x reference)
#include <cuda_runtime.h>
#include <math_constants.h>
#include <cstdint>

#define BSZ 2
#define TLEN 2048
#define DMODEL 1024
#define HN 16
#define DHEAD 64

// Q scratch: fp16 pairs, pre-scaled by log2(e)/sqrt(D), [B,H,T,32 words]. 8.4 MB.
__device__ uint32_t g_q[BSZ * HN * TLEN * 32];
// K fp16, V fp16, x/Wq bf16 scratch (16B chunks).
__device__ uint4 g_kb4[BSZ * HN * TLEN * 8];
__device__ uint4 g_vb4[BSZ * HN * TLEN * 8];
__device__ uint4 g_xb[BSZ * TLEN * DMODEL / 8];
__device__ uint4 g_wb[DMODEL * DMODEL / 8];

#define N4X (BSZ * TLEN * DMODEL / 8)   // 524288
#define N4W (DMODEL * DMODEL / 8)       // 131072

__device__ __forceinline__ uint32_t pkbf16(float hi, float lo) {
    uint32_t u;
    asm("cvt.rn.bf16x2.f32 %0, %1, %2;" : "=r"(u) : "f"(hi), "f"(lo));
    return u;
}
__device__ __forceinline__ uint32_t pkf16(float hi, float lo) {
    uint32_t u;
    asm("cvt.rn.f16x2.f32 %0, %1, %2;" : "=r"(u) : "f"(hi), "f"(lo));
    return u;
}
__device__ __forceinline__ float ex2f(float x) {
    float y;
    asm("ex2.approx.f32 %0, %1;" : "=f"(y) : "f"(x));
    return y;
}
__device__ __forceinline__ uint32_t hmax2(uint32_t a, uint32_t b) {
    uint32_t r;
    asm("max.f16x2 %0, %1, %2;" : "=r"(r) : "r"(a), "r"(b));
    return r;
}
__device__ __forceinline__ uint32_t hadd2(uint32_t a, uint32_t b) {
    uint32_t r;
    asm("add.f16x2 %0, %1, %2;" : "=r"(r) : "r"(a), "r"(b));
    return r;
}
__device__ __forceinline__ uint32_t hsub2(uint32_t a, uint32_t b) {
    uint32_t r;
    asm("sub.f16x2 %0, %1, %2;" : "=r"(r) : "r"(a), "r"(b));
    return r;
}
__device__ __forceinline__ uint32_t ex2_h2(uint32_t a) {
    uint32_t r;
    asm("ex2.approx.f16x2 %0, %1;" : "=r"(r) : "r"(a));
    return r;
}
__device__ __forceinline__ float h2lo_f(uint32_t h2) {
    float f;
    asm("{.reg .b16 lo, hi;\n\t mov.b32 {lo, hi}, %1;\n\t cvt.f32.f16 %0, lo;}"
        : "=f"(f) : "r"(h2));
    return f;
}
__device__ __forceinline__ float h2hi_f(uint32_t h2) {
    float f;
    asm("{.reg .b16 lo, hi;\n\t mov.b32 {lo, hi}, %1;\n\t cvt.f32.f16 %0, hi;}"
        : "=f"(f) : "r"(h2));
    return f;
}
// bf16 x bf16 -> f32 accumulate (Q GEMM)
__device__ __forceinline__ void mma_bf16(float d[4], const uint32_t a[4],
                                         uint32_t b0, uint32_t b1) {
    asm volatile(
        "mma.sync.aligned.m16n8k16.row.col.f32.bf16.bf16.f32 "
        "{%0,%1,%2,%3}, {%4,%5,%6,%7}, {%8,%9}, {%0,%1,%2,%3};\n"
        : "+f"(d[0]), "+f"(d[1]), "+f"(d[2]), "+f"(d[3])
        : "r"(a[0]), "r"(a[1]), "r"(a[2]), "r"(a[3]), "r"(b0), "r"(b1));
}
// f16 x f16 -> f32 accumulate (AV)
__device__ __forceinline__ void mma_f16(float d[4], const uint32_t a[4],
                                        uint32_t b0, uint32_t b1) {
    asm volatile(
        "mma.sync.aligned.m16n8k16.row.col.f32.f16.f16.f32 "
        "{%0,%1,%2,%3}, {%4,%5,%6,%7}, {%8,%9}, {%0,%1,%2,%3};\n"
        : "+f"(d[0]), "+f"(d[1]), "+f"(d[2]), "+f"(d[3])
        : "r"(a[0]), "r"(a[1]), "r"(a[2]), "r"(a[3]), "r"(b0), "r"(b1));
}
// f16 x f16 -> f16 accumulate (QK scores)
__device__ __forceinline__ void mma_f16_d16(uint32_t d[2], const uint32_t a[4],
                                            uint32_t b0, uint32_t b1) {
    asm volatile(
        "mma.sync.aligned.m16n8k16.row.col.f16.f16.f16.f16 "
        "{%0,%1}, {%2,%3,%4,%5}, {%6,%7}, {%0,%1};\n"
        : "+r"(d[0]), "+r"(d[1])
        : "r"(a[0]), "r"(a[1]), "r"(a[2]), "r"(a[3]), "r"(b0), "r"(b1));
}
__device__ __forceinline__ void ldsm4(uint32_t& d0, uint32_t& d1, uint32_t& d2,
                                      uint32_t& d3, uint32_t addr) {
    asm volatile("ldmatrix.sync.aligned.m8n8.x4.shared.b16 {%0,%1,%2,%3}, [%4];"
                 : "=r"(d0), "=r"(d1), "=r"(d2), "=r"(d3) : "r"(addr));
}
__device__ __forceinline__ void ldsm4t(uint32_t& d0, uint32_t& d1, uint32_t& d2,
                                       uint32_t& d3, uint32_t addr) {
    asm volatile("ldmatrix.sync.aligned.m8n8.x4.trans.shared.b16 {%0,%1,%2,%3}, [%4];"
                 : "=r"(d0), "=r"(d1), "=r"(d2), "=r"(d3) : "r"(addr));
}
#define CP16(dst, src) \
    asm volatile("cp.async.cg.shared.global [%0], [%1], 16;" :: "r"(dst), "l"(src))

// ---------------------------------------------------------------------------
// Kernel 0: convert x, Wq -> bf16 scratch. ONE uint4 per thread, many blocks
// (2048 x-blocks + 512 W-blocks) -> chip-wide latency hiding, no branching.
// ---------------------------------------------------------------------------
__global__ __launch_bounds__(256) void convert_xw(const float* __restrict__ x,
                                                  const float* __restrict__ w) {
    const int bid = blockIdx.x;
    const float4* src;
    uint4* dst;
    int i;
    if (bid < 2048) { src = (const float4*)x; dst = g_xb; i = bid * 256 + threadIdx.x; }
    else            { src = (const float4*)w; dst = g_wb; i = (bid - 2048) * 256 + threadIdx.x; }
    float4 a = src[2 * i], c = src[2 * i + 1];
    uint4 o;
    o.x = pkbf16(a.y, a.x); o.y = pkbf16(a.w, a.z);
    o.z = pkbf16(c.y, c.x); o.w = pkbf16(c.w, c.z);
    dst[i] = o;
}

// ---------------------------------------------------------------------------
// Kernel 1: Q projection GEMM (bf16 mma.sync, f32 acc) + k/v fp32->fp16
// conversion staged through the SAME cp.async pipeline (third smem region,
// 2 stages x 8KB). Each thread converts its own smem slot -> zero exposed
// global latency. smem 80KB, 2 blocks/SM. (Unchanged from R14.)
// ---------------------------------------------------------------------------
#define GEMM_SMEM 81920

__global__ __launch_bounds__(256, 2) void qgemm_kernel(const float* __restrict__ kin,
                                                       const float* __restrict__ vin) {
    extern __shared__ uint8_t dynsm[];
    const unsigned smbase = (unsigned)__cvta_generic_to_shared(dynsm);

    const int tid = threadIdx.x;
    const int lane = tid & 31;
    const int wid = tid >> 5;
    const int wm = wid >> 2;
    const int wn = wid & 3;
    const int gid = lane >> 2;
    const int qid = lane & 3;
    const int m0 = blockIdx.y * 128;
    const int n0 = blockIdx.x * 128;
    const int bid_lin = blockIdx.y * gridDim.x + blockIdx.x;   // 0..255

    const float4* csrc;
    uint4* cdst;
    int cbase = bid_lin * 4096;
    if (cbase < N4X) { csrc = (const float4*)kin; cdst = g_kb4; }
    else             { csrc = (const float4*)vin; cdst = g_vb4; cbase -= N4X; }

    const char* xg = (const char*)g_xb;
    const char* wg = (const char*)g_wb;

    auto fill = [&](int kt, int st) {
        unsigned sA = smbase + st * 32768;
        unsigned sB = sA + 16384;
#pragma unroll
        for (int p = 0; p < 4; p++) {
            int c = tid + p * 256;
            int row = c >> 3;
            int ch = c & 7;
            unsigned sw = (unsigned)((ch ^ (row & 7)) << 4);
            CP16(sA + row * 128 + sw, xg + (size_t)(m0 + row) * 2048 + kt * 128 + ch * 16);
        }
#pragma unroll
        for (int p = 0; p < 4; p++) {
            int c = tid + p * 256;
            int row = c >> 3;
            int ch = c & 7;
            unsigned sw = (unsigned)((ch ^ (row & 7)) << 4);
            CP16(sB + row * 128 + sw, wg + (size_t)(n0 + row) * 2048 + kt * 128 + ch * 16);
        }
        {
            unsigned kvd = smbase + 65536 + st * 8192 + tid * 32;
            const char* cs = (const char*)(csrc + 2 * (size_t)(cbase + kt * 256 + tid));
            CP16(kvd, cs);
            CP16(kvd + 16, cs + 16);
        }
        asm volatile("cp.async.commit_group;" ::: "memory");
    };

    float acc[4][4][4];
#pragma unroll
    for (int mf = 0; mf < 4; mf++)
#pragma unroll
        for (int nf = 0; nf < 4; nf++)
#pragma unroll
            for (int c = 0; c < 4; c++) acc[mf][nf][c] = 0.f;

    fill(0, 0);

    const int ar = wm * 64 + (lane & 7) + 8 * ((lane >> 3) & 1);
    const int ach = lane >> 4;
    const int bch = (lane >> 3) & 1;

    for (int kt = 0; kt < 16; kt++) {
        if (kt < 15) {
            fill(kt + 1, (kt + 1) & 1);
            asm volatile("cp.async.wait_group 1;" ::: "memory");
        } else {
            asm volatile("cp.async.wait_group 0;" ::: "memory");
        }
        __syncthreads();

        {
            const float4* p = (const float4*)(dynsm + 65536 + (kt & 1) * 8192 + tid * 32);
            float4 a = p[0], c = p[1];
            uint4 o;
            o.x = pkf16(a.y, a.x); o.y = pkf16(a.w, a.z);
            o.z = pkf16(c.y, c.x); o.w = pkf16(c.w, c.z);
            cdst[cbase + kt * 256 + tid] = o;
        }

        unsigned sA = smbase + (kt & 1) * 32768;
        unsigned sB = sA + 16384;

#pragma unroll
        for (int ks = 0; ks < 4; ks++) {
            uint32_t af[4][4];
#pragma unroll
            for (int mf = 0; mf < 4; mf++) {
                int row = ar + mf * 16;
                int ch = 2 * ks + ach;
                ldsm4(af[mf][0], af[mf][1], af[mf][2], af[mf][3],
                      sA + (unsigned)(row * 128 + ((ch ^ (row & 7)) << 4)));
            }
            uint32_t bf[4][2];
#pragma unroll
            for (int npair = 0; npair < 2; npair++) {
                int r = wn * 32 + npair * 16 + 8 * (lane >> 4) + (lane & 7);
                int ch = 2 * ks + bch;
                uint32_t d0, d1, d2, d3;
                ldsm4(d0, d1, d2, d3,
                      sB + (unsigned)(r * 128 + ((ch ^ (r & 7)) << 4)));
                bf[2 * npair][0] = d0; bf[2 * npair][1] = d1;
                bf[2 * npair + 1][0] = d2; bf[2 * npair + 1][1] = d3;
            }
#pragma unroll
            for (int mf = 0; mf < 4; mf++)
#pragma unroll
                for (int nf = 0; nf < 4; nf++)
                    mma_bf16(acc[mf][nf], af[mf], bf[nf][0], bf[nf][1]);
        }
        __syncthreads();
    }

    const float scale = 0.04508422f;   // log2(e)/32
#pragma unroll
    for (int mf = 0; mf < 4; mf++) {
#pragma unroll
        for (int nf = 0; nf < 4; nf++) {
            int m = m0 + wm * 64 + mf * 16 + gid;
            int n = n0 + wn * 32 + nf * 8 + 2 * qid;
            int b = m >> 11;
            int t = m & (TLEN - 1);
            int h = n >> 6;
            int pair = (n & 63) >> 1;
            size_t a0 = ((size_t)(b * HN + h) * TLEN + t) * 32 + pair;
            g_q[a0]       = pkf16(acc[mf][nf][1] * scale, acc[mf][nf][0] * scale);
            g_q[a0 + 256] = pkf16(acc[mf][nf][3] * scale, acc[mf][nf][2] * scale);
        }
    }
}

// ---------------------------------------------------------------------------
// Kernel 2: fp16 tensor-core causal flash attention + residual.
// Straight-line inner loops. QK f16 MMA (fp16 acc, S words = AV A-fragments),
// mask/max in f16x2, P = ex2.approx.f16x2(S - m), AV f16 MMA (f32 acc).
// l via scalar hadd2/cvt row-sums (off the tensor pipe; R13-verified math).
// ---------------------------------------------------------------------------
__global__ __launch_bounds__(128, 4) void attn_kernel(const float* __restrict__ x,
                                                      float* __restrict__ out) {
    __shared__ uint32_t smbuf[2 * 2 * 2048];   // [stage][K/V][64*32 u32] = 32KB

    const int tid = threadIdx.x;
    const int lane = tid & 31;
    const int wid = tid >> 5;
    const int qt = gridDim.x - 1 - blockIdx.x;   // heavy tiles first
    const int h = blockIdx.y;
    const int b = blockIdx.z;

    const int gid = lane >> 2;
    const int qid = lane & 3;
    const int i7 = lane & 7;
    const int half = (lane >> 3) & 1;
    const int koct = lane >> 4;

    const unsigned smbase = (unsigned)__cvta_generic_to_shared(smbuf);

    uint32_t qa[4][4];
    {
        const uint32_t* qg = g_q + ((size_t)((b * HN + h) * TLEN) + qt * 64 + wid * 16) * 32;
#pragma unroll
        for (int s = 0; s < 4; s++) {
            qa[s][0] = qg[gid * 32 + 8 * s + qid];
            qa[s][1] = qg[(gid + 8) * 32 + 8 * s + qid];
            qa[s][2] = qg[gid * 32 + 8 * s + qid + 4];
            qa[s][3] = qg[(gid + 8) * 32 + 8 * s + qid + 4];
        }
    }

    float oacc[8][4];
#pragma unroll
    for (int n = 0; n < 8; n++)
#pragma unroll
        for (int j = 0; j < 4; j++) oacc[n][j] = 0.f;
    float l0 = 0.f, l1 = 0.f;            // thread-partial row sums (f32)

    float m0 = -CUDART_INF_F, m1 = -CUDART_INF_F;

    const char* kgc = (const char*)(g_kb4 + (size_t)((b * HN + h) * TLEN) * 8);
    const char* vgc = (const char*)(g_vb4 + (size_t)((b * HN + h) * TLEN) * 8);

    auto fill = [&](int kt, int st) {
        const char* ks = kgc + (size_t)kt * 64 * 128;
        const char* vs = vgc + (size_t)kt * 64 * 128;
        unsigned kd = smbase + st * 16384;
        unsigned vd = kd + 8192;
#pragma unroll
        for (int i = 0; i < 4; i++) {
            int c = tid + i * 128;
            int key = c >> 3;
            int ch = c & 7;
            unsigned sw = (unsigned)((ch ^ (key & 7)) << 4);
            CP16(kd + key * 128 + sw, ks + key * 128 + ch * 16);
        }
#pragma unroll
        for (int i = 0; i < 4; i++) {
            int c = tid + i * 128;
            int key = c >> 3;
            int ch = c & 7;
            unsigned sw = (unsigned)((ch ^ (key & 7)) << 4);
            CP16(vd + key * 128 + sw, vs + key * 128 + ch * 16);
        }
        asm volatile("cp.async.commit_group;" ::: "memory");
    };

    fill(0, 0);

    for (int kt = 0; kt <= qt; kt++) {
        if (kt < qt) {
            fill(kt + 1, (kt + 1) & 1);
            asm volatile("cp.async.wait_group 1;" ::: "memory");
        } else {
            asm volatile("cp.async.wait_group 0;" ::: "memory");
        }
        __syncthreads();

        const unsigned kbuf = smbase + (kt & 1) * 16384;
        const unsigned vbuf = kbuf + 8192;

        // ---- S = Q K^T : f16 accumulate ----
        uint32_t sacc2[8][2];
#pragma unroll
        for (int n = 0; n < 8; n++) { sacc2[n][0] = 0u; sacc2[n][1] = 0u; }

        const int key0 = 8 * koct + i7;
#pragma unroll
        for (int s = 0; s < 4; s++) {
#pragma unroll
            for (int np = 0; np < 4; np++) {
                uint32_t d0, d1, d2, d3;
                unsigned addr = kbuf + (unsigned)((16 * np + key0) * 128 +
                                                  (((2 * s + half) ^ i7) << 4));
                ldsm4(d0, d1, d2, d3, addr);
                mma_f16_d16(sacc2[2 * np], qa[s], d0, d1);
                mma_f16_d16(sacc2[2 * np + 1], qa[s], d2, d3);
            }
        }

        // ---- causal mask (diagonal tile only): add 0 / -inf in f16 ----
        const int row0 = wid * 16 + gid;
        const int row1 = row0 + 8;
        if (kt == qt) {
#pragma unroll
            for (int n = 0; n < 8; n++) {
                int c = 8 * n + 2 * qid;
                uint32_t w0 = ((c > row0) ? 0xFC00u : 0u) |
                              ((c + 1 > row0) ? 0xFC000000u : 0u);
                uint32_t w1 = ((c > row1) ? 0xFC00u : 0u) |
                              ((c + 1 > row1) ? 0xFC000000u : 0u);
                sacc2[n][0] = hadd2(sacc2[n][0], w0);
                sacc2[n][1] = hadd2(sacc2[n][1], w1);
            }
        }

        // ---- row max in f16x2 ----
        uint32_t mx0 = sacc2[0][0], mx1 = sacc2[0][1];
#pragma unroll
        for (int n = 1; n < 8; n++) {
            mx0 = hmax2(mx0, sacc2[n][0]);
            mx1 = hmax2(mx1, sacc2[n][1]);
        }
        mx0 = hmax2(mx0, __shfl_xor_sync(0xffffffffu, mx0, 1));
        mx0 = hmax2(mx0, __shfl_xor_sync(0xffffffffu, mx0, 2));
        mx1 = hmax2(mx1, __shfl_xor_sync(0xffffffffu, mx1, 1));
        mx1 = hmax2(mx1, __shfl_xor_sync(0xffffffffu, mx1, 2));
        const float t0 = fmaxf(h2lo_f(mx0), h2hi_f(mx0));
        const float t1 = fmaxf(h2lo_f(mx1), h2hi_f(mx1));

        const float mn0 = fmaxf(m0, t0);
        const float mn1 = fmaxf(m1, t1);
        const float corr0 = ex2f(m0 - mn0);
        const float corr1 = ex2f(m1 - mn1);
        m0 = mn0; m1 = mn1;

#pragma unroll
        for (int n = 0; n < 8; n++) {
            oacc[n][0] *= corr0; oacc[n][1] *= corr0;
            oacc[n][2] *= corr1; oacc[n][3] *= corr1;
        }
        l0 *= corr0;
        l1 *= corr1;

        // ---- P = exp2(S - m) in f16x2; words ARE the AV A-fragments ----
        const uint32_t mn0_2 = pkf16(mn0, mn0);
        const uint32_t mn1_2 = pkf16(mn1, mn1);
        uint32_t pu[4][4];
#pragma unroll
        for (int s = 0; s < 4; s++) {
            pu[s][0] = ex2_h2(hsub2(sacc2[2 * s][0], mn0_2));
            pu[s][1] = ex2_h2(hsub2(sacc2[2 * s][1], mn1_2));
            pu[s][2] = ex2_h2(hsub2(sacc2[2 * s + 1][0], mn0_2));
            pu[s][3] = ex2_h2(hsub2(sacc2[2 * s + 1][1], mn1_2));
        }

        // ---- l += row-sum of P (scalar; off the tensor pipe) ----
#pragma unroll
        for (int s = 0; s < 4; s++) {
            uint32_t r0 = hadd2(pu[s][0], pu[s][2]);
            uint32_t r1 = hadd2(pu[s][1], pu[s][3]);
            l0 += h2lo_f(r0) + h2hi_f(r0);
            l1 += h2lo_f(r1) + h2hi_f(r1);
        }

        // ---- O += P V (f16, f32 acc) ----
#pragma unroll
        for (int nd = 0; nd < 4; nd++) {
#pragma unroll
            for (int s = 0; s < 4; s++) {
                uint32_t d0, d1, d2, d3;
                int keyv = 16 * s + 8 * half + i7;
                unsigned addr = vbuf + (unsigned)(keyv * 128 +
                                                  (((2 * nd + koct) ^ i7) << 4));
                ldsm4t(d0, d1, d2, d3, addr);
                mma_f16(oacc[2 * nd], pu[s], d0, d1);
                mma_f16(oacc[2 * nd + 1], pu[s], d2, d3);
            }
        }
        __syncthreads();
    }

    // ---- epilogue: finish l reduction (4 lanes per row), normalize, store ----
    l0 += __shfl_xor_sync(0xffffffffu, l0, 1);
    l0 += __shfl_xor_sync(0xffffffffu, l0, 2);
    l1 += __shfl_xor_sync(0xffffffffu, l1, 1);
    l1 += __shfl_xor_sync(0xffffffffu, l1, 2);
    const float inv0 = 1.f / l0;
    const float inv1 = 1.f / l1;

    const int row0 = qt * 64 + wid * 16 + gid;
    const int row1 = row0 + 8;
    const size_t base0 = (size_t)(b * TLEN + row0) * DMODEL + h * DHEAD + 2 * qid;
    const size_t base1 = (size_t)(b * TLEN + row1) * DMODEL + h * DHEAD + 2 * qid;
#pragma unroll
    for (int nd = 0; nd < 8; nd++) {
        float2 x0 = *(const float2*)(x + base0 + 8 * nd);
        float2 x1 = *(const float2*)(x + base1 + 8 * nd);
        float2 r0, r1;
        r0.x = x0.x + oacc[nd][0] * inv0;
        r0.y = x0.y + oacc[nd][1] * inv0;
        r1.x = x1.x + oacc[nd][2] * inv1;
        r1.y = x1.y + oacc[nd][3] * inv1;
        *(float2*)(out + base0 + 8 * nd) = r0;
        *(float2*)(out + base1 + 8 * nd) = r1;
    }
}

extern "C" void kernel_launch(void* const* d_in, const int* in_sizes, int n_in,
                              void* d_out, int out_size) {
    const float* x  = (const float*)d_in[0];   // [B,T,D]
    const float* k  = (const float*)d_in[1];   // [B,H,T,DH]
    const float* v  = (const float*)d_in[2];   // [B,H,T,DH]
    const float* Wq = (const float*)d_in[3];   // [D,D]
    float* out = (float*)d_out;                // [B,T,D]

    // 1) convert x, Wq: 1 uint4/thread, 2560 blocks (chip-wide latency hiding)
    convert_xw<<<2560, 256>>>(x, Wq);

    // 2) GEMM + k/v conversion staged through the cp.async pipeline
    cudaFuncSetAttribute(qgemm_kernel, cudaFuncAttributeMaxDynamicSharedMemorySize,
                         GEMM_SMEM);
    dim3 g1(DMODEL / 128, (BSZ * TLEN) / 128); // (8, 32)
    qgemm_kernel<<<g1, 256, GEMM_SMEM>>>(k, v);

    // 3) attention + residual
    dim3 g2(TLEN / 64, HN, BSZ);               // (32, 16, 2)
    attn_kernel<<<g2, 128>>>(x, out);
}

// round 16
// speedup vs baseline: 1.0750x; 1.0750x over previous
#include <cuda_runtime.h>
#include <math_constants.h>
#include <cstdint>

#define BSZ 2
#define TLEN 2048
#define DMODEL 1024
#define HN 16
#define DHEAD 64

// Q scratch: fp16 pairs, pre-scaled by log2(e)/sqrt(D), [B,H,T,32 words]. 8.4 MB.
__device__ uint32_t g_q[BSZ * HN * TLEN * 32];
// K fp16, V fp16, x/Wq bf16 scratch (16B chunks).
__device__ uint4 g_kb4[BSZ * HN * TLEN * 8];
__device__ uint4 g_vb4[BSZ * HN * TLEN * 8];
__device__ uint4 g_xb[BSZ * TLEN * DMODEL / 8];
__device__ uint4 g_wb[DMODEL * DMODEL / 8];

#define N4X (BSZ * TLEN * DMODEL / 8)   // 524288
#define N4W (DMODEL * DMODEL / 8)       // 131072

__device__ __forceinline__ uint32_t pkbf16(float hi, float lo) {
    uint32_t u;
    asm("cvt.rn.bf16x2.f32 %0, %1, %2;" : "=r"(u) : "f"(hi), "f"(lo));
    return u;
}
__device__ __forceinline__ uint32_t pkf16(float hi, float lo) {
    uint32_t u;
    asm("cvt.rn.f16x2.f32 %0, %1, %2;" : "=r"(u) : "f"(hi), "f"(lo));
    return u;
}
__device__ __forceinline__ float ex2f(float x) {
    float y;
    asm("ex2.approx.f32 %0, %1;" : "=f"(y) : "f"(x));
    return y;
}
__device__ __forceinline__ uint32_t hmax2(uint32_t a, uint32_t b) {
    uint32_t r;
    asm("max.f16x2 %0, %1, %2;" : "=r"(r) : "r"(a), "r"(b));
    return r;
}
__device__ __forceinline__ uint32_t hadd2(uint32_t a, uint32_t b) {
    uint32_t r;
    asm("add.f16x2 %0, %1, %2;" : "=r"(r) : "r"(a), "r"(b));
    return r;
}
__device__ __forceinline__ uint32_t hsub2(uint32_t a, uint32_t b) {
    uint32_t r;
    asm("sub.f16x2 %0, %1, %2;" : "=r"(r) : "r"(a), "r"(b));
    return r;
}
__device__ __forceinline__ uint32_t ex2_h2(uint32_t a) {
    uint32_t r;
    asm("ex2.approx.f16x2 %0, %1;" : "=r"(r) : "r"(a));
    return r;
}
__device__ __forceinline__ float h2lo_f(uint32_t h2) {
    float f;
    asm("{.reg .b16 lo, hi;\n\t mov.b32 {lo, hi}, %1;\n\t cvt.f32.f16 %0, lo;}"
        : "=f"(f) : "r"(h2));
    return f;
}
__device__ __forceinline__ float h2hi_f(uint32_t h2) {
    float f;
    asm("{.reg .b16 lo, hi;\n\t mov.b32 {lo, hi}, %1;\n\t cvt.f32.f16 %0, hi;}"
        : "=f"(f) : "r"(h2));
    return f;
}
// bf16 x bf16 -> f32 accumulate (Q GEMM)
__device__ __forceinline__ void mma_bf16(float d[4], const uint32_t a[4],
                                         uint32_t b0, uint32_t b1) {
    asm volatile(
        "mma.sync.aligned.m16n8k16.row.col.f32.bf16.bf16.f32 "
        "{%0,%1,%2,%3}, {%4,%5,%6,%7}, {%8,%9}, {%0,%1,%2,%3};\n"
        : "+f"(d[0]), "+f"(d[1]), "+f"(d[2]), "+f"(d[3])
        : "r"(a[0]), "r"(a[1]), "r"(a[2]), "r"(a[3]), "r"(b0), "r"(b1));
}
// f16 x f16 -> f32 accumulate (AV, l-sum)
__device__ __forceinline__ void mma_f16(float d[4], const uint32_t a[4],
                                        uint32_t b0, uint32_t b1) {
    asm volatile(
        "mma.sync.aligned.m16n8k16.row.col.f32.f16.f16.f32 "
        "{%0,%1,%2,%3}, {%4,%5,%6,%7}, {%8,%9}, {%0,%1,%2,%3};\n"
        : "+f"(d[0]), "+f"(d[1]), "+f"(d[2]), "+f"(d[3])
        : "r"(a[0]), "r"(a[1]), "r"(a[2]), "r"(a[3]), "r"(b0), "r"(b1));
}
// f16 x f16 -> f16 accumulate (QK scores)
__device__ __forceinline__ void mma_f16_d16(uint32_t d[2], const uint32_t a[4],
                                            uint32_t b0, uint32_t b1) {
    asm volatile(
        "mma.sync.aligned.m16n8k16.row.col.f16.f16.f16.f16 "
        "{%0,%1}, {%2,%3,%4,%5}, {%6,%7}, {%0,%1};\n"
        : "+r"(d[0]), "+r"(d[1])
        : "r"(a[0]), "r"(a[1]), "r"(a[2]), "r"(a[3]), "r"(b0), "r"(b1));
}
__device__ __forceinline__ void ldsm4(uint32_t& d0, uint32_t& d1, uint32_t& d2,
                                      uint32_t& d3, uint32_t addr) {
    asm volatile("ldmatrix.sync.aligned.m8n8.x4.shared.b16 {%0,%1,%2,%3}, [%4];"
                 : "=r"(d0), "=r"(d1), "=r"(d2), "=r"(d3) : "r"(addr));
}
__device__ __forceinline__ void ldsm4t(uint32_t& d0, uint32_t& d1, uint32_t& d2,
                                       uint32_t& d3, uint32_t addr) {
    asm volatile("ldmatrix.sync.aligned.m8n8.x4.trans.shared.b16 {%0,%1,%2,%3}, [%4];"
                 : "=r"(d0), "=r"(d1), "=r"(d2), "=r"(d3) : "r"(addr));
}
#define CP16(dst, src) \
    asm volatile("cp.async.cg.shared.global [%0], [%1], 16;" :: "r"(dst), "l"(src))

// ---------------------------------------------------------------------------
// Kernel 0: convert x, Wq -> bf16 scratch. ONE uint4 per thread, many blocks
// (2048 x-blocks + 512 W-blocks) -> chip-wide latency hiding, no branching.
// ---------------------------------------------------------------------------
__global__ __launch_bounds__(256) void convert_xw(const float* __restrict__ x,
                                                  const float* __restrict__ w) {
    const int bid = blockIdx.x;
    const float4* src;
    uint4* dst;
    int i;
    if (bid < 2048) { src = (const float4*)x; dst = g_xb; i = bid * 256 + threadIdx.x; }
    else            { src = (const float4*)w; dst = g_wb; i = (bid - 2048) * 256 + threadIdx.x; }
    float4 a = src[2 * i], c = src[2 * i + 1];
    uint4 o;
    o.x = pkbf16(a.y, a.x); o.y = pkbf16(a.w, a.z);
    o.z = pkbf16(c.y, c.x); o.w = pkbf16(c.w, c.z);
    dst[i] = o;
}

// ---------------------------------------------------------------------------
// Kernel 1: Q projection GEMM (bf16 mma.sync, f32 acc) + k/v fp32->fp16
// conversion staged through the SAME cp.async pipeline. (Unchanged from R14.)
// ---------------------------------------------------------------------------
#define GEMM_SMEM 81920

__global__ __launch_bounds__(256, 2) void qgemm_kernel(const float* __restrict__ kin,
                                                       const float* __restrict__ vin) {
    extern __shared__ uint8_t dynsm[];
    const unsigned smbase = (unsigned)__cvta_generic_to_shared(dynsm);

    const int tid = threadIdx.x;
    const int lane = tid & 31;
    const int wid = tid >> 5;
    const int wm = wid >> 2;
    const int wn = wid & 3;
    const int gid = lane >> 2;
    const int qid = lane & 3;
    const int m0 = blockIdx.y * 128;
    const int n0 = blockIdx.x * 128;
    const int bid_lin = blockIdx.y * gridDim.x + blockIdx.x;   // 0..255

    const float4* csrc;
    uint4* cdst;
    int cbase = bid_lin * 4096;
    if (cbase < N4X) { csrc = (const float4*)kin; cdst = g_kb4; }
    else             { csrc = (const float4*)vin; cdst = g_vb4; cbase -= N4X; }

    const char* xg = (const char*)g_xb;
    const char* wg = (const char*)g_wb;

    auto fill = [&](int kt, int st) {
        unsigned sA = smbase + st * 32768;
        unsigned sB = sA + 16384;
#pragma unroll
        for (int p = 0; p < 4; p++) {
            int c = tid + p * 256;
            int row = c >> 3;
            int ch = c & 7;
            unsigned sw = (unsigned)((ch ^ (row & 7)) << 4);
            CP16(sA + row * 128 + sw, xg + (size_t)(m0 + row) * 2048 + kt * 128 + ch * 16);
        }
#pragma unroll
        for (int p = 0; p < 4; p++) {
            int c = tid + p * 256;
            int row = c >> 3;
            int ch = c & 7;
            unsigned sw = (unsigned)((ch ^ (row & 7)) << 4);
            CP16(sB + row * 128 + sw, wg + (size_t)(n0 + row) * 2048 + kt * 128 + ch * 16);
        }
        {
            unsigned kvd = smbase + 65536 + st * 8192 + tid * 32;
            const char* cs = (const char*)(csrc + 2 * (size_t)(cbase + kt * 256 + tid));
            CP16(kvd, cs);
            CP16(kvd + 16, cs + 16);
        }
        asm volatile("cp.async.commit_group;" ::: "memory");
    };

    float acc[4][4][4];
#pragma unroll
    for (int mf = 0; mf < 4; mf++)
#pragma unroll
        for (int nf = 0; nf < 4; nf++)
#pragma unroll
            for (int c = 0; c < 4; c++) acc[mf][nf][c] = 0.f;

    fill(0, 0);

    const int ar = wm * 64 + (lane & 7) + 8 * ((lane >> 3) & 1);
    const int ach = lane >> 4;
    const int bch = (lane >> 3) & 1;

    for (int kt = 0; kt < 16; kt++) {
        if (kt < 15) {
            fill(kt + 1, (kt + 1) & 1);
            asm volatile("cp.async.wait_group 1;" ::: "memory");
        } else {
            asm volatile("cp.async.wait_group 0;" ::: "memory");
        }
        __syncthreads();

        {
            const float4* p = (const float4*)(dynsm + 65536 + (kt & 1) * 8192 + tid * 32);
            float4 a = p[0], c = p[1];
            uint4 o;
            o.x = pkf16(a.y, a.x); o.y = pkf16(a.w, a.z);
            o.z = pkf16(c.y, c.x); o.w = pkf16(c.w, c.z);
            cdst[cbase + kt * 256 + tid] = o;
        }

        unsigned sA = smbase + (kt & 1) * 32768;
        unsigned sB = sA + 16384;

#pragma unroll
        for (int ks = 0; ks < 4; ks++) {
            uint32_t af[4][4];
#pragma unroll
            for (int mf = 0; mf < 4; mf++) {
                int row = ar + mf * 16;
                int ch = 2 * ks + ach;
                ldsm4(af[mf][0], af[mf][1], af[mf][2], af[mf][3],
                      sA + (unsigned)(row * 128 + ((ch ^ (row & 7)) << 4)));
            }
            uint32_t bf[4][2];
#pragma unroll
            for (int npair = 0; npair < 2; npair++) {
                int r = wn * 32 + npair * 16 + 8 * (lane >> 4) + (lane & 7);
                int ch = 2 * ks + bch;
                uint32_t d0, d1, d2, d3;
                ldsm4(d0, d1, d2, d3,
                      sB + (unsigned)(r * 128 + ((ch ^ (r & 7)) << 4)));
                bf[2 * npair][0] = d0; bf[2 * npair][1] = d1;
                bf[2 * npair + 1][0] = d2; bf[2 * npair + 1][1] = d3;
            }
#pragma unroll
            for (int mf = 0; mf < 4; mf++)
#pragma unroll
                for (int nf = 0; nf < 4; nf++)
                    mma_bf16(acc[mf][nf], af[mf], bf[nf][0], bf[nf][1]);
        }
        __syncthreads();
    }

    const float scale = 0.04508422f;   // log2(e)/32
#pragma unroll
    for (int mf = 0; mf < 4; mf++) {
#pragma unroll
        for (int nf = 0; nf < 4; nf++) {
            int m = m0 + wm * 64 + mf * 16 + gid;
            int n = n0 + wn * 32 + nf * 8 + 2 * qid;
            int b = m >> 11;
            int t = m & (TLEN - 1);
            int h = n >> 6;
            int pair = (n & 63) >> 1;
            size_t a0 = ((size_t)(b * HN + h) * TLEN + t) * 32 + pair;
            g_q[a0]       = pkf16(acc[mf][nf][1] * scale, acc[mf][nf][0] * scale);
            g_q[a0 + 256] = pkf16(acc[mf][nf][3] * scale, acc[mf][nf][2] * scale);
        }
    }
}

// ---------------------------------------------------------------------------
// Kernel 2: fp16 tensor-core causal flash attention + residual.
// R14 math (ones-column l MMA, straight-line loops). NEW: causal tile
// PAIRING — each block handles q-tiles (p0, 31-p0): uniform 33 kv-tile-units
// per block, 512 blocks -> one perfectly balanced wave (no quantization).
// ---------------------------------------------------------------------------
__global__ __launch_bounds__(128, 4) void attn_kernel(const float* __restrict__ x,
                                                      float* __restrict__ out) {
    __shared__ uint32_t smbuf[2 * 2 * 2048];   // [stage][K/V][64*32 u32] = 32KB

    const int tid = threadIdx.x;
    const int lane = tid & 31;
    const int wid = tid >> 5;
    const int h = blockIdx.y;
    const int b = blockIdx.z;

    const int gid = lane >> 2;
    const int qid = lane & 3;
    const int i7 = lane & 7;
    const int half = (lane >> 3) & 1;
    const int koct = lane >> 4;

    const uint32_t ONE2 = 0x3C003C00u;   // f16x2 {1.0, 1.0}
    const int NQT = TLEN / 64;            // 32

    const unsigned smbase = (unsigned)__cvta_generic_to_shared(smbuf);

    const char* kgc = (const char*)(g_kb4 + (size_t)((b * HN + h) * TLEN) * 8);
    const char* vgc = (const char*)(g_vb4 + (size_t)((b * HN + h) * TLEN) * 8);

    auto fill = [&](int kt, int st) {
        const char* ks = kgc + (size_t)kt * 64 * 128;
        const char* vs = vgc + (size_t)kt * 64 * 128;
        unsigned kd = smbase + st * 16384;
        unsigned vd = kd + 8192;
#pragma unroll
        for (int i = 0; i < 4; i++) {
            int c = tid + i * 128;
            int key = c >> 3;
            int ch = c & 7;
            unsigned sw = (unsigned)((ch ^ (key & 7)) << 4);
            CP16(kd + key * 128 + sw, ks + key * 128 + ch * 16);
        }
#pragma unroll
        for (int i = 0; i < 4; i++) {
            int c = tid + i * 128;
            int key = c >> 3;
            int ch = c & 7;
            unsigned sw = (unsigned)((ch ^ (key & 7)) << 4);
            CP16(vd + key * 128 + sw, vs + key * 128 + ch * 16);
        }
        asm volatile("cp.async.commit_group;" ::: "memory");
    };

    // Two complementary q-tiles: uniform total work (qtA+1)+(qtB+1) = 33.
#pragma unroll 1
    for (int pp = 0; pp < 2; pp++) {
        const int qt = pp ? (NQT - 1 - (int)blockIdx.x) : (int)blockIdx.x;

        // ---- Q fragments for this tile ----
        uint32_t qa[4][4];
        {
            const uint32_t* qg = g_q + ((size_t)((b * HN + h) * TLEN) + qt * 64 + wid * 16) * 32;
#pragma unroll
            for (int s = 0; s < 4; s++) {
                qa[s][0] = qg[gid * 32 + 8 * s + qid];
                qa[s][1] = qg[(gid + 8) * 32 + 8 * s + qid];
                qa[s][2] = qg[gid * 32 + 8 * s + qid + 4];
                qa[s][3] = qg[(gid + 8) * 32 + 8 * s + qid + 4];
            }
        }

        float oacc[8][4];
#pragma unroll
        for (int n = 0; n < 8; n++)
#pragma unroll
            for (int j = 0; j < 4; j++) oacc[n][j] = 0.f;
        float lacc[4] = {0.f, 0.f, 0.f, 0.f};
        float m0 = -CUDART_INF_F, m1 = -CUDART_INF_F;

        fill(0, 0);

#pragma unroll 1
        for (int kt = 0; kt <= qt; kt++) {
            if (kt < qt) {
                fill(kt + 1, (kt + 1) & 1);
                asm volatile("cp.async.wait_group 1;" ::: "memory");
            } else {
                asm volatile("cp.async.wait_group 0;" ::: "memory");
            }
            __syncthreads();

            const unsigned kbuf = smbase + (kt & 1) * 16384;
            const unsigned vbuf = kbuf + 8192;

            // ---- S = Q K^T : f16 accumulate ----
            uint32_t sacc2[8][2];
#pragma unroll
            for (int n = 0; n < 8; n++) { sacc2[n][0] = 0u; sacc2[n][1] = 0u; }

            const int key0 = 8 * koct + i7;
#pragma unroll
            for (int s = 0; s < 4; s++) {
#pragma unroll
                for (int np = 0; np < 4; np++) {
                    uint32_t d0, d1, d2, d3;
                    unsigned addr = kbuf + (unsigned)((16 * np + key0) * 128 +
                                                      (((2 * s + half) ^ i7) << 4));
                    ldsm4(d0, d1, d2, d3, addr);
                    mma_f16_d16(sacc2[2 * np], qa[s], d0, d1);
                    mma_f16_d16(sacc2[2 * np + 1], qa[s], d2, d3);
                }
            }

            // ---- causal mask (diagonal tile only): add 0 / -inf in f16 ----
            const int row0 = wid * 16 + gid;
            const int row1 = row0 + 8;
            if (kt == qt) {
#pragma unroll
                for (int n = 0; n < 8; n++) {
                    int c = 8 * n + 2 * qid;
                    uint32_t w0 = ((c > row0) ? 0xFC00u : 0u) |
                                  ((c + 1 > row0) ? 0xFC000000u : 0u);
                    uint32_t w1 = ((c > row1) ? 0xFC00u : 0u) |
                                  ((c + 1 > row1) ? 0xFC000000u : 0u);
                    sacc2[n][0] = hadd2(sacc2[n][0], w0);
                    sacc2[n][1] = hadd2(sacc2[n][1], w1);
                }
            }

            // ---- row max in f16x2 ----
            uint32_t mx0 = sacc2[0][0], mx1 = sacc2[0][1];
#pragma unroll
            for (int n = 1; n < 8; n++) {
                mx0 = hmax2(mx0, sacc2[n][0]);
                mx1 = hmax2(mx1, sacc2[n][1]);
            }
            mx0 = hmax2(mx0, __shfl_xor_sync(0xffffffffu, mx0, 1));
            mx0 = hmax2(mx0, __shfl_xor_sync(0xffffffffu, mx0, 2));
            mx1 = hmax2(mx1, __shfl_xor_sync(0xffffffffu, mx1, 1));
            mx1 = hmax2(mx1, __shfl_xor_sync(0xffffffffu, mx1, 2));
            const float t0 = fmaxf(h2lo_f(mx0), h2hi_f(mx0));
            const float t1 = fmaxf(h2lo_f(mx1), h2hi_f(mx1));

            const float mn0 = fmaxf(m0, t0);
            const float mn1 = fmaxf(m1, t1);
            const float corr0 = ex2f(m0 - mn0);
            const float corr1 = ex2f(m1 - mn1);
            m0 = mn0; m1 = mn1;

#pragma unroll
            for (int n = 0; n < 8; n++) {
                oacc[n][0] *= corr0; oacc[n][1] *= corr0;
                oacc[n][2] *= corr1; oacc[n][3] *= corr1;
            }
            lacc[0] *= corr0;
            lacc[2] *= corr1;

            // ---- P = exp2(S - m) in f16x2; words ARE the AV A-fragments ----
            const uint32_t mn0_2 = pkf16(mn0, mn0);
            const uint32_t mn1_2 = pkf16(mn1, mn1);
            uint32_t pu[4][4];
#pragma unroll
            for (int s = 0; s < 4; s++) {
                pu[s][0] = ex2_h2(hsub2(sacc2[2 * s][0], mn0_2));
                pu[s][1] = ex2_h2(hsub2(sacc2[2 * s][1], mn1_2));
                pu[s][2] = ex2_h2(hsub2(sacc2[2 * s + 1][0], mn0_2));
                pu[s][3] = ex2_h2(hsub2(sacc2[2 * s + 1][1], mn1_2));
            }

            // ---- l += P @ ones (row sums via tensor core) ----
#pragma unroll
            for (int s = 0; s < 4; s++)
                mma_f16(lacc, pu[s], ONE2, ONE2);

            // ---- O += P V (f16, f32 acc) ----
#pragma unroll
            for (int nd = 0; nd < 4; nd++) {
#pragma unroll
                for (int s = 0; s < 4; s++) {
                    uint32_t d0, d1, d2, d3;
                    int keyv = 16 * s + 8 * half + i7;
                    unsigned addr = vbuf + (unsigned)(keyv * 128 +
                                                      (((2 * nd + koct) ^ i7) << 4));
                    ldsm4t(d0, d1, d2, d3, addr);
                    mma_f16(oacc[2 * nd], pu[s], d0, d1);
                    mma_f16(oacc[2 * nd + 1], pu[s], d2, d3);
                }
            }
            __syncthreads();
        }

        // ---- epilogue for this tile ----
        const float inv0 = 1.f / lacc[0];
        const float inv1 = 1.f / lacc[2];

        const int row0 = qt * 64 + wid * 16 + gid;
        const int row1 = row0 + 8;
        const size_t base0 = (size_t)(b * TLEN + row0) * DMODEL + h * DHEAD + 2 * qid;
        const size_t base1 = (size_t)(b * TLEN + row1) * DMODEL + h * DHEAD + 2 * qid;
#pragma unroll
        for (int nd = 0; nd < 8; nd++) {
            float2 x0 = *(const float2*)(x + base0 + 8 * nd);
            float2 x1 = *(const float2*)(x + base1 + 8 * nd);
            float2 r0, r1;
            r0.x = x0.x + oacc[nd][0] * inv0;
            r0.y = x0.y + oacc[nd][1] * inv0;
            r1.x = x1.x + oacc[nd][2] * inv1;
            r1.y = x1.y + oacc[nd][3] * inv1;
            *(float2*)(out + base0 + 8 * nd) = r0;
            *(float2*)(out + base1 + 8 * nd) = r1;
        }
    }
}

extern "C" void kernel_launch(void* const* d_in, const int* in_sizes, int n_in,
                              void* d_out, int out_size) {
    const float* x  = (const float*)d_in[0];   // [B,T,D]
    const float* k  = (const float*)d_in[1];   // [B,H,T,DH]
    const float* v  = (const float*)d_in[2];   // [B,H,T,DH]
    const float* Wq = (const float*)d_in[3];   // [D,D]
    float* out = (float*)d_out;                // [B,T,D]

    // 1) convert x, Wq: 1 uint4/thread, 2560 blocks
    convert_xw<<<2560, 256>>>(x, Wq);

    // 2) GEMM + k/v conversion staged through the cp.async pipeline
    cudaFuncSetAttribute(qgemm_kernel, cudaFuncAttributeMaxDynamicSharedMemorySize,
                         GEMM_SMEM);
    dim3 g1(DMODEL / 128, (BSZ * TLEN) / 128); // (8, 32)
    qgemm_kernel<<<g1, 256, GEMM_SMEM>>>(k, v);

    // 3) attention + residual: paired causal tiles, 512 uniform blocks
    dim3 g2(TLEN / 128, HN, BSZ);              // (16, 16, 2)
    attn_kernel<<<g2, 128>>>(x, out);
}